// round 8
// baseline (speedup 1.0000x reference)
#include <cuda_runtime.h>
#include <cstdint>

#define NN 4096
#define CC 8
#define BB 2
#define PP 16          // B*C
#define MAXDET 100
#define SCORE_THR 0.01f
#define INVKEY26 0x3FFFFFFu      // > any valid key26 (max valid = 0x35C28F5)

// ---------------- static scratch (no runtime allocation allowed) ----------------
// cand key layout: [key26:26 | c:3 | n:12]  (41 bits) ; pad = ~0ull
__device__ unsigned long long g_cand[BB][CC * MAXDET];

// exact replica of: fl(inter / max(union,1e-9)) > 0.5   (reference fp32 rounding)
__device__ __forceinline__ bool iou_gt_half(float4 a, float aa, float4 b, float ab) {
    float ix1 = fmaxf(a.x, b.x);
    float iy1 = fmaxf(a.y, b.y);
    float ix2 = fminf(a.z, b.z);
    float iy2 = fminf(a.w, b.w);
    float iw = fmaxf(ix2 - ix1, 0.0f);
    float ih = fmaxf(iy2 - iy1, 0.0f);
    float inter = iw * ih;
    float uni = (aa + ab) - inter;
    float d = fmaf(-0.5f, uni, inter);        // sign is exact
    bool gt = d > 0.0f;
    if (fabsf(d) <= 1e-5f * uni) {            // borderline: do the real division
        gt = __fdiv_rn(inter, fmaxf(uni, 1e-9f)) > 0.5f;
    }
    return gt;
}

// smem layout (dynamic): sbox[4096] f4 | skeys[4096] u64 | hist[4096] u32 | off[4096] u32 | wsum[32]
#define SM_BOX   0
#define SM_KEYS  65536
#define SM_HIST  98304
#define SM_OFF   114688
#define SM_WSUM  131072
#define SM_TOTAL 131200

// ---- fused: bucket-sort by (score, idx) + early-stop greedy NMS (warp 0) --------
__global__ __launch_bounds__(1024) void sortnms_kernel(const float* __restrict__ cls,
                                                       const float* __restrict__ boxes) {
    extern __shared__ char dyn[];
    float4*             sbox  = reinterpret_cast<float4*>(dyn + SM_BOX);
    unsigned long long* skeys = reinterpret_cast<unsigned long long*>(dyn + SM_KEYS);
    unsigned int*       hist  = reinterpret_cast<unsigned int*>(dyn + SM_HIST);
    unsigned int*       off   = reinterpret_cast<unsigned int*>(dyn + SM_OFF);
    unsigned int*       wsum  = reinterpret_cast<unsigned int*>(dyn + SM_WSUM);

    int p = blockIdx.x;          // 0..15
    int b = p >> 3;
    int c = p & 7;
    int tid = threadIdx.x;
    int lane = tid & 31, wid = tid >> 5;

    const float4* bx4 = reinterpret_cast<const float4*>(boxes) + (b << 12);

    // zero histogram + stage boxes into smem
#pragma unroll
    for (int e = 0; e < 4; e++) hist[tid + e * 1024] = 0u;
#pragma unroll
    for (int e = 0; e < 4; e++) { int i = tid + e * 1024; sbox[i] = bx4[i]; }

    // build 38-bit keys [key26 | n:12]; key26 = 0x3F800000 - bits(s), exact order
    unsigned long long keys[4];
    unsigned int bkt[4];
#pragma unroll
    for (int e = 0; e < 4; e++) {
        int n = tid * 4 + e;
        float s = cls[(((b << 12) + n) << 3) + c];
        unsigned int sb = __float_as_uint(s);
        unsigned int k26;
        if (s > SCORE_THR) {
            k26 = (sb >= 0x3F800000u) ? 0u : (0x3F800000u - sb);   // clamp guard
        } else {
            k26 = INVKEY26;                                        // sorts last
        }
        keys[e] = ((unsigned long long)k26 << 12) | (unsigned int)n;
        bkt[e] = k26 >> 14;
    }
    __syncthreads();

#pragma unroll
    for (int e = 0; e < 4; e++) atomicAdd(&hist[bkt[e]], 1u);
    __syncthreads();

    // exclusive scan of 4096 bins (4/thread + warp shfl + warp-of-warps)
    unsigned int c0 = hist[tid * 4], c1 = hist[tid * 4 + 1],
                 c2 = hist[tid * 4 + 2], c3 = hist[tid * 4 + 3];
    unsigned int s01 = c0 + c1, sum = s01 + c2 + c3;
    unsigned int inc = sum;
#pragma unroll
    for (int d = 1; d < 32; d <<= 1) {
        unsigned int v = __shfl_up_sync(0xffffffffu, inc, d);
        if (lane >= d) inc += v;
    }
    if (lane == 31) wsum[wid] = inc;
    __syncthreads();
    if (wid == 0) {
        unsigned int v = wsum[lane], wi = v;
#pragma unroll
        for (int d = 1; d < 32; d <<= 1) {
            unsigned int u = __shfl_up_sync(0xffffffffu, wi, d);
            if (lane >= d) wi += u;
        }
        wsum[lane] = wi - v;     // exclusive
    }
    __syncthreads();
    unsigned int base = wsum[wid] + (inc - sum);
    off[tid * 4 + 0] = base;
    off[tid * 4 + 1] = base + c0;
    off[tid * 4 + 2] = base + s01;
    off[tid * 4 + 3] = base + s01 + c2;
    __syncthreads();

    // scatter (off[b] becomes end-of-bucket)
#pragma unroll
    for (int e = 0; e < 4; e++) {
        unsigned int pos = atomicAdd(&off[bkt[e]], 1u);
        skeys[pos] = keys[e];
    }
    __syncthreads();

    // per-bucket insertion sort (tiny runs; skip invalid bucket 4095 — never read)
#pragma unroll
    for (int e = 0; e < 4; e++) {
        int bk = tid + e * 1024;
        int sz = (int)hist[bk];
        if (bk != 4095 && sz > 1) {
            int st = (int)off[bk] - sz;
            for (int i = 1; i < sz; i++) {
                unsigned long long v = skeys[st + i];
                int q = st + i;
                while (q > st && skeys[q - 1] > v) { skeys[q] = skeys[q - 1]; q--; }
                skeys[q] = v;
            }
        }
    }
    __syncthreads();

    if (tid >= 32) return;       // warp 0 does the (serial) NMS scan

    // kept set in registers: lane holds kept k with (k&31)==lane, slot k>>5
    float4 kb0, kb1, kb2, kb3;
    float ka0 = 0.f, ka1 = 0.f, ka2 = 0.f, ka3 = 0.f;
    kb0 = kb1 = kb2 = kb3 = make_float4(0.f, 0.f, 0.f, 0.f);
    int kept = 0;

    unsigned long long keyA = skeys[0];
    float4 bA = sbox[(int)(keyA & 4095u)];

    for (int j = 0; j < NN && kept < MAXDET; j++) {
        unsigned long long key = keyA;
        if ((unsigned int)(key >> 12) == INVKEY26) break;   // rest invalid
        float4 bj = bA;
        keyA = (j + 1 < NN) ? skeys[j + 1] : ~0ull;
        bA = sbox[(int)(keyA & 4095u)];                      // prefetch (LDS)

        float aj = (bj.z - bj.x) * (bj.w - bj.y);
        bool sup = false;
        if (lane      < kept) sup |= iou_gt_half(kb0, ka0, bj, aj);
        if (lane + 32 < kept) sup |= iou_gt_half(kb1, ka1, bj, aj);
        if (lane + 64 < kept) sup |= iou_gt_half(kb2, ka2, bj, aj);
        if (lane + 96 < kept) sup |= iou_gt_half(kb3, ka3, bj, aj);
        unsigned int bal = __ballot_sync(0xffffffffu, sup);

        if (bal == 0u) {                                     // kept
            if (lane == (kept & 31)) {
                switch (kept >> 5) {
                    case 0: kb0 = bj; ka0 = aj; break;
                    case 1: kb1 = bj; ka1 = aj; break;
                    case 2: kb2 = bj; ka2 = aj; break;
                    default: kb3 = bj; ka3 = aj; break;
                }
            }
            if (lane == 0) {
                unsigned int n = (unsigned int)(key & 4095u);
                g_cand[b][c * MAXDET + kept] =
                    ((key >> 12) << 15) | (unsigned int)((c << 12) | n);
            }
            kept++;
        }
    }

    // pad unused slots (sort last; decoded as "no detection")
    for (int t = kept + lane; t < MAXDET; t += 32)
        g_cand[b][c * MAXDET + t] = 0xFFFFFFFFFFFFFFFFull;
}

// ---- per-batch: rank 800 candidates by counting, write top-100 rows -------------
__global__ __launch_bounds__(1024) void topk_kernel(const float* __restrict__ boxes,
                                                    const float* __restrict__ rot,
                                                    const float* __restrict__ trans,
                                                    float* __restrict__ out) {
    __shared__ unsigned long long sk[CC * MAXDET];
    int b = blockIdx.x;
    int tid = threadIdx.x;

    if (tid < CC * MAXDET) sk[tid] = g_cand[b][tid];
    __syncthreads();

    if (tid < CC * MAXDET) {
        unsigned long long my = sk[tid];
        int rank = 0;
#pragma unroll 4
        for (int j = 0; j < CC * MAXDET; j++) {
            unsigned long long kj = sk[j];
            rank += (kj < my || (kj == my && j < tid)) ? 1 : 0;
        }
        if (rank < MAXDET) {
            bool ok = (my != 0xFFFFFFFFFFFFFFFFull);
            float b0 = -1.f, b1 = -1.f, b2 = -1.f, b3 = -1.f;
            float sc = -1.f, lab = -1.f;
            float r0 = -1.f, r1 = -1.f, r2 = -1.f;
            float t0 = -1.f, t1 = -1.f, t2 = -1.f;
            if (ok) {
                unsigned int k26 = (unsigned int)(my >> 15);
                int c = (int)((my >> 12) & 7u);
                int n = (int)(my & 4095u);
                sc = __uint_as_float(0x3F800000u - k26);   // exact decode
                lab = (float)c;
                float4 bb4 = reinterpret_cast<const float4*>(boxes)[(b << 12) + n];
                b0 = bb4.x; b1 = bb4.y; b2 = bb4.z; b3 = bb4.w;
                int base3 = ((b << 12) + n) * 3;
                r0 = rot[base3 + 0]; r1 = rot[base3 + 1]; r2 = rot[base3 + 2];
                t0 = trans[base3 + 0]; t1 = trans[base3 + 1]; t2 = trans[base3 + 2];
            }
            // layout: boxes[B,100,4] | scores[B,100] | labels[B,100] | rot[B,100,3] | trans[B,100,3]
            int r = rank;
            float* obox = out;                       // 0    .. 800
            float* osc  = out + BB * MAXDET * 4;     // 800  .. 1000
            float* olab = osc + BB * MAXDET;         // 1000 .. 1200
            float* orot = olab + BB * MAXDET;        // 1200 .. 1800
            float* otr  = orot + BB * MAXDET * 3;    // 1800 .. 2400
            obox[(b * MAXDET + r) * 4 + 0] = b0;
            obox[(b * MAXDET + r) * 4 + 1] = b1;
            obox[(b * MAXDET + r) * 4 + 2] = b2;
            obox[(b * MAXDET + r) * 4 + 3] = b3;
            osc[b * MAXDET + r] = sc;
            olab[b * MAXDET + r] = lab;
            orot[(b * MAXDET + r) * 3 + 0] = r0;
            orot[(b * MAXDET + r) * 3 + 1] = r1;
            orot[(b * MAXDET + r) * 3 + 2] = r2;
            otr[(b * MAXDET + r) * 3 + 0] = t0;
            otr[(b * MAXDET + r) * 3 + 1] = t1;
            otr[(b * MAXDET + r) * 3 + 2] = t2;
        }
    }
}

extern "C" void kernel_launch(void* const* d_in, const int* in_sizes, int n_in,
                              void* d_out, int out_size) {
    const float* boxes = (const float*)d_in[0];
    const float* cls   = (const float*)d_in[1];
    const float* rot   = (const float*)d_in[2];
    const float* trans = (const float*)d_in[3];
    float* out = (float*)d_out;
    (void)in_sizes; (void)n_in; (void)out_size;

    cudaFuncSetAttribute(sortnms_kernel,
                         cudaFuncAttributeMaxDynamicSharedMemorySize, SM_TOTAL);

    sortnms_kernel<<<PP, 1024, SM_TOTAL>>>(cls, boxes);
    topk_kernel<<<BB, 1024>>>(boxes, rot, trans, out);
}

// round 9
// speedup vs baseline: 1.6076x; 1.6076x over previous
#include <cuda_runtime.h>
#include <cstdint>

#define NN 4096
#define CC 8
#define BB 2
#define PP 16          // B*C
#define MAXDET 100
#define SCORE_THR 0.01f
#define INVKEY26 0x3FFFFFFu      // > any valid key26 (max valid = 0x35C28F5)

// ---------------- static scratch (no runtime allocation allowed) ----------------
// cand key layout: [key26:26 | c:3 | n:12]  (41 bits); pads: [INVKEY26 | c:3 | slot:12]
// all 1600 keys globally unique; per-class list sorted ascending
__device__ unsigned long long g_cand[BB][CC * MAXDET];

// exact replica of: fl(inter / max(union,1e-9)) > 0.5   (reference fp32 rounding)
__device__ __forceinline__ bool iou_gt_half(float4 a, float aa, float4 b, float ab) {
    float ix1 = fmaxf(a.x, b.x);
    float iy1 = fmaxf(a.y, b.y);
    float ix2 = fminf(a.z, b.z);
    float iy2 = fminf(a.w, b.w);
    float iw = fmaxf(ix2 - ix1, 0.0f);
    float ih = fmaxf(iy2 - iy1, 0.0f);
    float inter = iw * ih;
    float uni = (aa + ab) - inter;
    float d = fmaf(-0.5f, uni, inter);        // sign is exact
    bool gt = d > 0.0f;
    if (fabsf(d) <= 1e-5f * uni) {            // borderline: do the real division
        gt = __fdiv_rn(inter, fmaxf(uni, 1e-9f)) > 0.5f;
    }
    return gt;
}

// smem layout (dynamic): sbox[4096] f4 | skeys[4096] u64 | hist[4096] u32 | off[4096] u32 | wsum[32]
#define SM_BOX   0
#define SM_KEYS  65536
#define SM_HIST  98304
#define SM_OFF   114688
#define SM_WSUM  131072
#define SM_TOTAL 131200

// ---- fused: bucket-sort by (score, idx) + early-stop greedy NMS (warp 0) --------
__global__ __launch_bounds__(1024) void sortnms_kernel(const float* __restrict__ cls,
                                                       const float* __restrict__ boxes) {
    extern __shared__ char dyn[];
    float4*             sbox  = reinterpret_cast<float4*>(dyn + SM_BOX);
    unsigned long long* skeys = reinterpret_cast<unsigned long long*>(dyn + SM_KEYS);
    unsigned int*       hist  = reinterpret_cast<unsigned int*>(dyn + SM_HIST);
    unsigned int*       off   = reinterpret_cast<unsigned int*>(dyn + SM_OFF);
    unsigned int*       wsum  = reinterpret_cast<unsigned int*>(dyn + SM_WSUM);

    int p = blockIdx.x;          // 0..15
    int b = p >> 3;
    int c = p & 7;
    int tid = threadIdx.x;
    int lane = tid & 31, wid = tid >> 5;

    const float4* bx4 = reinterpret_cast<const float4*>(boxes) + (b << 12);
    // cls[B][N][8] as float4 pairs: (n,c) -> float4 index n*2 + (c>>2), comp c&3
    const float4* cls4 = reinterpret_cast<const float4*>(cls) + ((size_t)b << 13);
    int chalf = c >> 2, ccomp = c & 3;

    // zero histogram + stage boxes into smem
#pragma unroll
    for (int e = 0; e < 4; e++) hist[tid + e * 1024] = 0u;
#pragma unroll
    for (int e = 0; e < 4; e++) { int i = tid + e * 1024; sbox[i] = __ldg(&bx4[i]); }

    // build 38-bit keys [key26 | n:12]; key26 = 0x3F800000 - bits(s), exact order
    unsigned long long keys[4];
    unsigned int bkt[4];
#pragma unroll
    for (int e = 0; e < 4; e++) {
        int n = tid * 4 + e;
        float4 v = __ldg(&cls4[n * 2 + chalf]);
        float s = (ccomp == 0) ? v.x : (ccomp == 1) ? v.y : (ccomp == 2) ? v.z : v.w;
        unsigned int sb = __float_as_uint(s);
        unsigned int k26;
        if (s > SCORE_THR) {
            k26 = (sb >= 0x3F800000u) ? 0u : (0x3F800000u - sb);   // clamp guard
        } else {
            k26 = INVKEY26;                                        // sorts last
        }
        keys[e] = ((unsigned long long)k26 << 12) | (unsigned int)n;
        bkt[e] = k26 >> 14;
    }
    __syncthreads();

#pragma unroll
    for (int e = 0; e < 4; e++) atomicAdd(&hist[bkt[e]], 1u);
    __syncthreads();

    // exclusive scan of 4096 bins (4/thread + warp shfl + warp-of-warps)
    uint4 hv = reinterpret_cast<uint4*>(hist)[tid];
    unsigned int c0 = hv.x, c1 = hv.y, c2 = hv.z, c3 = hv.w;
    unsigned int s01 = c0 + c1, sum = s01 + c2 + c3;
    unsigned int inc = sum;
#pragma unroll
    for (int d = 1; d < 32; d <<= 1) {
        unsigned int v = __shfl_up_sync(0xffffffffu, inc, d);
        if (lane >= d) inc += v;
    }
    if (lane == 31) wsum[wid] = inc;
    __syncthreads();
    if (wid == 0) {
        unsigned int v = wsum[lane], wi = v;
#pragma unroll
        for (int d = 1; d < 32; d <<= 1) {
            unsigned int u = __shfl_up_sync(0xffffffffu, wi, d);
            if (lane >= d) wi += u;
        }
        wsum[lane] = wi - v;     // exclusive
    }
    __syncthreads();
    unsigned int base = wsum[wid] + (inc - sum);
    reinterpret_cast<uint4*>(off)[tid] =
        make_uint4(base, base + c0, base + s01, base + s01 + c2);
    __syncthreads();

    // scatter (off[bk] becomes end-of-bucket)
#pragma unroll
    for (int e = 0; e < 4; e++) {
        unsigned int pos = atomicAdd(&off[bkt[e]], 1u);
        skeys[pos] = keys[e];
    }
    __syncthreads();

    // per-bucket insertion sort (tiny runs; skip invalid bucket 4095 — never sorted-read)
#pragma unroll
    for (int e = 0; e < 4; e++) {
        int bk = tid + e * 1024;
        int sz = (int)hist[bk];
        if (bk != 4095 && sz > 1) {
            int st = (int)off[bk] - sz;
            for (int i = 1; i < sz; i++) {
                unsigned long long v = skeys[st + i];
                int q = st + i;
                while (q > st && skeys[q - 1] > v) { skeys[q] = skeys[q - 1]; q--; }
                skeys[q] = v;
            }
        }
    }
    __syncthreads();

    if (tid >= 32) return;       // warp 0 does the (serial) NMS scan

    // kept set in registers: lane holds kept k with (k&31)==lane, slot k>>5
    float4 kb0, kb1, kb2, kb3;
    float ka0 = 0.f, ka1 = 0.f, ka2 = 0.f, ka3 = 0.f;
    kb0 = kb1 = kb2 = kb3 = make_float4(0.f, 0.f, 0.f, 0.f);
    int kept = 0;

    unsigned long long keyA = skeys[0];
    float4 bA = sbox[(int)(keyA & 4095u)];

    for (int j = 0; j < NN && kept < MAXDET; j++) {
        unsigned long long key = keyA;
        if ((unsigned int)(key >> 12) == INVKEY26) break;   // rest invalid
        float4 bj = bA;
        keyA = (j + 1 < NN) ? skeys[j + 1] : ~0ull;
        bA = sbox[(int)(keyA & 4095u)];                      // prefetch (LDS)

        float aj = (bj.z - bj.x) * (bj.w - bj.y);
        bool sup = false;
        if (lane      < kept) sup |= iou_gt_half(kb0, ka0, bj, aj);
        if (lane + 32 < kept) sup |= iou_gt_half(kb1, ka1, bj, aj);
        if (lane + 64 < kept) sup |= iou_gt_half(kb2, ka2, bj, aj);
        if (lane + 96 < kept) sup |= iou_gt_half(kb3, ka3, bj, aj);
        unsigned int bal = __ballot_sync(0xffffffffu, sup);

        if (bal == 0u) {                                     // kept
            if (lane == (kept & 31)) {
                switch (kept >> 5) {
                    case 0: kb0 = bj; ka0 = aj; break;
                    case 1: kb1 = bj; ka1 = aj; break;
                    case 2: kb2 = bj; ka2 = aj; break;
                    default: kb3 = bj; ka3 = aj; break;
                }
            }
            if (lane == 0) {
                unsigned int n = (unsigned int)(key & 4095u);
                g_cand[b][c * MAXDET + kept] =
                    ((key >> 12) << 15) | (unsigned int)((c << 12) | n);
            }
            kept++;
        }
    }

    // pad unused slots: unique keys > all valid keys (per-class ascending)
    for (int t = kept + lane; t < MAXDET; t += 32)
        g_cand[b][c * MAXDET + t] =
            ((unsigned long long)INVKEY26 << 15) | (unsigned int)((c << 12) | t);
}

// ---- per-batch: rank via 7 binary searches over sorted class lists --------------
__global__ __launch_bounds__(1024) void topk_kernel(const float* __restrict__ boxes,
                                                    const float* __restrict__ rot,
                                                    const float* __restrict__ trans,
                                                    float* __restrict__ out) {
    __shared__ unsigned long long sk[CC * MAXDET];
    int b = blockIdx.x;
    int tid = threadIdx.x;

    if (tid < CC * MAXDET) sk[tid] = g_cand[b][tid];
    __syncthreads();

    if (tid < CC * MAXDET) {
        unsigned long long my = sk[tid];
        int cl = tid / MAXDET;
        int rank = tid - cl * MAXDET;    // slot within own (sorted, unique) list
#pragma unroll
        for (int c2 = 0; c2 < CC; c2++) {
            if (c2 == cl) continue;
            const unsigned long long* lst = &sk[c2 * MAXDET];
            int lo = 0, hi = MAXDET;     // lower_bound (keys globally unique)
            while (lo < hi) {
                int mid = (lo + hi) >> 1;
                if (lst[mid] < my) lo = mid + 1; else hi = mid;
            }
            rank += lo;
        }

        if (rank < MAXDET) {
            unsigned int k26 = (unsigned int)(my >> 15);
            bool ok = (k26 != INVKEY26);
            float b0 = -1.f, b1 = -1.f, b2 = -1.f, b3 = -1.f;
            float sc = -1.f, lab = -1.f;
            float r0 = -1.f, r1 = -1.f, r2 = -1.f;
            float t0 = -1.f, t1 = -1.f, t2 = -1.f;
            if (ok) {
                int c = (int)((my >> 12) & 7u);
                int n = (int)(my & 4095u);
                sc = __uint_as_float(0x3F800000u - k26);   // exact decode
                lab = (float)c;
                float4 bb4 = reinterpret_cast<const float4*>(boxes)[(b << 12) + n];
                b0 = bb4.x; b1 = bb4.y; b2 = bb4.z; b3 = bb4.w;
                int base3 = ((b << 12) + n) * 3;
                r0 = rot[base3 + 0]; r1 = rot[base3 + 1]; r2 = rot[base3 + 2];
                t0 = trans[base3 + 0]; t1 = trans[base3 + 1]; t2 = trans[base3 + 2];
            }
            // layout: boxes[B,100,4] | scores[B,100] | labels[B,100] | rot[B,100,3] | trans[B,100,3]
            int r = rank;
            float* obox = out;                       // 0    .. 800
            float* osc  = out + BB * MAXDET * 4;     // 800  .. 1000
            float* olab = osc + BB * MAXDET;         // 1000 .. 1200
            float* orot = olab + BB * MAXDET;        // 1200 .. 1800
            float* otr  = orot + BB * MAXDET * 3;    // 1800 .. 2400
            obox[(b * MAXDET + r) * 4 + 0] = b0;
            obox[(b * MAXDET + r) * 4 + 1] = b1;
            obox[(b * MAXDET + r) * 4 + 2] = b2;
            obox[(b * MAXDET + r) * 4 + 3] = b3;
            osc[b * MAXDET + r] = sc;
            olab[b * MAXDET + r] = lab;
            orot[(b * MAXDET + r) * 3 + 0] = r0;
            orot[(b * MAXDET + r) * 3 + 1] = r1;
            orot[(b * MAXDET + r) * 3 + 2] = r2;
            otr[(b * MAXDET + r) * 3 + 0] = t0;
            otr[(b * MAXDET + r) * 3 + 1] = t1;
            otr[(b * MAXDET + r) * 3 + 2] = t2;
        }
    }
}

extern "C" void kernel_launch(void* const* d_in, const int* in_sizes, int n_in,
                              void* d_out, int out_size) {
    const float* boxes = (const float*)d_in[0];
    const float* cls   = (const float*)d_in[1];
    const float* rot   = (const float*)d_in[2];
    const float* trans = (const float*)d_in[3];
    float* out = (float*)d_out;
    (void)in_sizes; (void)n_in; (void)out_size;

    cudaFuncSetAttribute(sortnms_kernel,
                         cudaFuncAttributeMaxDynamicSharedMemorySize, SM_TOTAL);

    sortnms_kernel<<<PP, 1024, SM_TOTAL>>>(cls, boxes);
    topk_kernel<<<BB, 1024>>>(boxes, rot, trans, out);
}

// round 10
// speedup vs baseline: 1.6288x; 1.0132x over previous
#include <cuda_runtime.h>
#include <cstdint>

#define NN 4096
#define CC 8
#define BB 2
#define PP 16          // B*C
#define MAXDET 100
#define SCORE_THR 0.01f
#define INVKEY26 0x3FFFFFFu      // > any valid key26 (max valid = 0x35C28F5)

// ---------------- static scratch (no runtime allocation allowed) ----------------
// cand key layout: [key26:26 | c:3 | n:12]  (41 bits); pads: [INVKEY26 | c:3 | slot:12]
// all 1600 keys globally unique; per-class list sorted ascending
__device__ unsigned long long g_cand[BB][CC * MAXDET];
__device__ unsigned int       g_ticket[BB];    // monotone; (t&7)==7 -> last CTA of batch

// exact replica of: fl(inter / max(union,1e-9)) > 0.5   (reference fp32 rounding)
__device__ __forceinline__ bool iou_gt_half(float4 a, float aa, float4 b, float ab) {
    float ix1 = fmaxf(a.x, b.x);
    float iy1 = fmaxf(a.y, b.y);
    float ix2 = fminf(a.z, b.z);
    float iy2 = fminf(a.w, b.w);
    float iw = fmaxf(ix2 - ix1, 0.0f);
    float ih = fmaxf(iy2 - iy1, 0.0f);
    float inter = iw * ih;
    float uni = (aa + ab) - inter;
    float d = fmaf(-0.5f, uni, inter);        // sign is exact
    bool gt = d > 0.0f;
    if (fabsf(d) <= 1e-5f * uni) {            // borderline: do the real division
        gt = __fdiv_rn(inter, fmaxf(uni, 1e-9f)) > 0.5f;
    }
    return gt;
}

// smem layout (dynamic): sbox[4096] f4 | skeys[4096] u64 | hist[4096] u32 | off[4096] u32 | wsum[32]
#define SM_BOX   0
#define SM_KEYS  65536
#define SM_HIST  98304
#define SM_OFF   114688
#define SM_WSUM  131072
#define SM_TOTAL 131200

// ---- fully fused: bucket-sort + greedy NMS + (last CTA per batch) top-100 -------
__global__ __launch_bounds__(1024) void fused_kernel(const float* __restrict__ cls,
                                                     const float* __restrict__ boxes,
                                                     const float* __restrict__ rot,
                                                     const float* __restrict__ trans,
                                                     float* __restrict__ out) {
    extern __shared__ char dyn[];
    float4*             sbox  = reinterpret_cast<float4*>(dyn + SM_BOX);
    unsigned long long* skeys = reinterpret_cast<unsigned long long*>(dyn + SM_KEYS);
    unsigned int*       hist  = reinterpret_cast<unsigned int*>(dyn + SM_HIST);
    unsigned int*       off   = reinterpret_cast<unsigned int*>(dyn + SM_OFF);
    unsigned int*       wsum  = reinterpret_cast<unsigned int*>(dyn + SM_WSUM);
    __shared__ int      sLast;

    int p = blockIdx.x;          // 0..15
    int b = p >> 3;
    int c = p & 7;
    int tid = threadIdx.x;
    int lane = tid & 31, wid = tid >> 5;

    const float4* bx4 = reinterpret_cast<const float4*>(boxes) + (b << 12);
    // cls[B][N][8] as float4 pairs: (n,c) -> float4 index n*2 + (c>>2), comp c&3
    const float4* cls4 = reinterpret_cast<const float4*>(cls) + ((size_t)b << 13);
    int chalf = c >> 2, ccomp = c & 3;

    // zero histogram (uint4) + stage boxes into smem
    reinterpret_cast<uint4*>(hist)[tid] = make_uint4(0u, 0u, 0u, 0u);
#pragma unroll
    for (int e = 0; e < 4; e++) { int i = tid + e * 1024; sbox[i] = __ldg(&bx4[i]); }

    // build 38-bit keys [key26 | n:12]; key26 = 0x3F800000 - bits(s), exact order
    unsigned long long keys[4];
    unsigned int bkt[4];
#pragma unroll
    for (int e = 0; e < 4; e++) {
        int n = tid * 4 + e;
        float4 v = __ldg(&cls4[n * 2 + chalf]);
        float s = (ccomp == 0) ? v.x : (ccomp == 1) ? v.y : (ccomp == 2) ? v.z : v.w;
        unsigned int sb = __float_as_uint(s);
        unsigned int k26;
        if (s > SCORE_THR) {
            k26 = (sb >= 0x3F800000u) ? 0u : (0x3F800000u - sb);   // clamp guard
        } else {
            k26 = INVKEY26;                                        // sorts last
        }
        keys[e] = ((unsigned long long)k26 << 12) | (unsigned int)n;
        bkt[e] = k26 >> 14;
    }
    __syncthreads();

#pragma unroll
    for (int e = 0; e < 4; e++) atomicAdd(&hist[bkt[e]], 1u);
    __syncthreads();

    // exclusive scan of 4096 bins (4/thread + warp shfl + warp-of-warps)
    uint4 hv = reinterpret_cast<uint4*>(hist)[tid];
    unsigned int c0 = hv.x, c1 = hv.y, c2 = hv.z, c3 = hv.w;
    unsigned int s01 = c0 + c1, sum = s01 + c2 + c3;
    unsigned int inc = sum;
#pragma unroll
    for (int d = 1; d < 32; d <<= 1) {
        unsigned int v = __shfl_up_sync(0xffffffffu, inc, d);
        if (lane >= d) inc += v;
    }
    if (lane == 31) wsum[wid] = inc;
    __syncthreads();
    if (wid == 0) {
        unsigned int v = wsum[lane], wi = v;
#pragma unroll
        for (int d = 1; d < 32; d <<= 1) {
            unsigned int u = __shfl_up_sync(0xffffffffu, wi, d);
            if (lane >= d) wi += u;
        }
        wsum[lane] = wi - v;     // exclusive
    }
    __syncthreads();
    unsigned int base = wsum[wid] + (inc - sum);
    reinterpret_cast<uint4*>(off)[tid] =
        make_uint4(base, base + c0, base + s01, base + s01 + c2);
    __syncthreads();

    // scatter (off[bk] becomes end-of-bucket)
#pragma unroll
    for (int e = 0; e < 4; e++) {
        unsigned int pos = atomicAdd(&off[bkt[e]], 1u);
        skeys[pos] = keys[e];
    }
    __syncthreads();

    // per-bucket insertion sort (tiny runs; skip invalid bucket 4095 — never sorted-read)
#pragma unroll
    for (int e = 0; e < 4; e++) {
        int bk = tid + e * 1024;
        int sz = (int)hist[bk];
        if (bk != 4095 && sz > 1) {
            int st = (int)off[bk] - sz;
            for (int i = 1; i < sz; i++) {
                unsigned long long v = skeys[st + i];
                int q = st + i;
                while (q > st && skeys[q - 1] > v) { skeys[q] = skeys[q - 1]; q--; }
                skeys[q] = v;
            }
        }
    }
    __syncthreads();

    // -------- warp 0: serial greedy NMS with early stop; others wait -------------
    if (wid == 0) {
        // kept set in registers: lane holds kept k with (k&31)==lane, slot k>>5
        float4 kb0, kb1, kb2, kb3;
        float ka0 = 0.f, ka1 = 0.f, ka2 = 0.f, ka3 = 0.f;
        kb0 = kb1 = kb2 = kb3 = make_float4(0.f, 0.f, 0.f, 0.f);
        int kept = 0;

        unsigned long long keyA = skeys[0];
        float4 bA = sbox[(int)(keyA & 4095u)];

        for (int j = 0; j < NN && kept < MAXDET; j++) {
            unsigned long long key = keyA;
            if ((unsigned int)(key >> 12) == INVKEY26) break;   // rest invalid
            float4 bj = bA;
            keyA = (j + 1 < NN) ? skeys[j + 1] : ~0ull;
            bA = sbox[(int)(keyA & 4095u)];                      // prefetch (LDS)

            float aj = (bj.z - bj.x) * (bj.w - bj.y);
            bool sup = false;
            if (lane      < kept) sup |= iou_gt_half(kb0, ka0, bj, aj);
            if (lane + 32 < kept) sup |= iou_gt_half(kb1, ka1, bj, aj);
            if (lane + 64 < kept) sup |= iou_gt_half(kb2, ka2, bj, aj);
            if (lane + 96 < kept) sup |= iou_gt_half(kb3, ka3, bj, aj);
            unsigned int bal = __ballot_sync(0xffffffffu, sup);

            if (bal == 0u) {                                     // kept
                if (lane == (kept & 31)) {
                    switch (kept >> 5) {
                        case 0: kb0 = bj; ka0 = aj; break;
                        case 1: kb1 = bj; ka1 = aj; break;
                        case 2: kb2 = bj; ka2 = aj; break;
                        default: kb3 = bj; ka3 = aj; break;
                    }
                }
                if (lane == 0) {
                    unsigned int n = (unsigned int)(key & 4095u);
                    g_cand[b][c * MAXDET + kept] =
                        ((key >> 12) << 15) | (unsigned int)((c << 12) | n);
                }
                kept++;
            }
        }

        // pad unused slots: unique keys > all valid keys (per-class ascending)
        for (int t = kept + lane; t < MAXDET; t += 32)
            g_cand[b][c * MAXDET + t] =
                ((unsigned long long)INVKEY26 << 15) | (unsigned int)((c << 12) | t);

        __threadfence();                 // publish this CTA's g_cand (all lanes wrote)
        __syncwarp();
        if (lane == 0) {
            unsigned int t = atomicAdd(&g_ticket[b], 1u);
            int last = ((t & 7u) == 7u) ? 1 : 0;
            __threadfence();             // acquire: order g_cand reads after ticket
            sLast = last;
        }
    }
    __syncthreads();

    if (!sLast) return;

    // -------- last CTA of batch b: rank 800 candidates, write top-100 ------------
    unsigned long long* sk = skeys;      // reuse (our own sort data is dead now)
    if (tid < CC * MAXDET) sk[tid] = __ldcg(&g_cand[b][tid]);   // L2-coherent read
    __syncthreads();

    if (tid < CC * MAXDET) {
        unsigned long long my = sk[tid];
        int cl = tid / MAXDET;
        int rank = tid - cl * MAXDET;    // slot within own (sorted, unique) list
#pragma unroll
        for (int c2 = 0; c2 < CC; c2++) {
            if (c2 == cl) continue;
            const unsigned long long* lst = &sk[c2 * MAXDET];
            int lo = 0, hi = MAXDET;     // lower_bound (keys globally unique)
            while (lo < hi) {
                int mid = (lo + hi) >> 1;
                if (lst[mid] < my) lo = mid + 1; else hi = mid;
            }
            rank += lo;
        }

        if (rank < MAXDET) {
            unsigned int k26 = (unsigned int)(my >> 15);
            bool ok = (k26 != INVKEY26);
            float b0 = -1.f, b1 = -1.f, b2 = -1.f, b3 = -1.f;
            float sc = -1.f, lab = -1.f;
            float r0 = -1.f, r1 = -1.f, r2 = -1.f;
            float t0 = -1.f, t1 = -1.f, t2 = -1.f;
            if (ok) {
                int cdec = (int)((my >> 12) & 7u);
                int n = (int)(my & 4095u);
                sc = __uint_as_float(0x3F800000u - k26);   // exact decode
                lab = (float)cdec;
                float4 bb4 = sbox[n];                      // our batch's boxes (smem)
                b0 = bb4.x; b1 = bb4.y; b2 = bb4.z; b3 = bb4.w;
                int base3 = ((b << 12) + n) * 3;
                r0 = rot[base3 + 0]; r1 = rot[base3 + 1]; r2 = rot[base3 + 2];
                t0 = trans[base3 + 0]; t1 = trans[base3 + 1]; t2 = trans[base3 + 2];
            }
            // layout: boxes[B,100,4] | scores[B,100] | labels[B,100] | rot[B,100,3] | trans[B,100,3]
            int r = rank;
            float* obox = out;                       // 0    .. 800
            float* osc  = out + BB * MAXDET * 4;     // 800  .. 1000
            float* olab = osc + BB * MAXDET;         // 1000 .. 1200
            float* orot = olab + BB * MAXDET;        // 1200 .. 1800
            float* otr  = orot + BB * MAXDET * 3;    // 1800 .. 2400
            obox[(b * MAXDET + r) * 4 + 0] = b0;
            obox[(b * MAXDET + r) * 4 + 1] = b1;
            obox[(b * MAXDET + r) * 4 + 2] = b2;
            obox[(b * MAXDET + r) * 4 + 3] = b3;
            osc[b * MAXDET + r] = sc;
            olab[b * MAXDET + r] = lab;
            orot[(b * MAXDET + r) * 3 + 0] = r0;
            orot[(b * MAXDET + r) * 3 + 1] = r1;
            orot[(b * MAXDET + r) * 3 + 2] = r2;
            otr[(b * MAXDET + r) * 3 + 0] = t0;
            otr[(b * MAXDET + r) * 3 + 1] = t1;
            otr[(b * MAXDET + r) * 3 + 2] = t2;
        }
    }
}

extern "C" void kernel_launch(void* const* d_in, const int* in_sizes, int n_in,
                              void* d_out, int out_size) {
    const float* boxes = (const float*)d_in[0];
    const float* cls   = (const float*)d_in[1];
    const float* rot   = (const float*)d_in[2];
    const float* trans = (const float*)d_in[3];
    float* out = (float*)d_out;
    (void)in_sizes; (void)n_in; (void)out_size;

    cudaFuncSetAttribute(fused_kernel,
                         cudaFuncAttributeMaxDynamicSharedMemorySize, SM_TOTAL);

    fused_kernel<<<PP, 1024, SM_TOTAL>>>(cls, boxes, rot, trans, out);
}

// round 11
// speedup vs baseline: 3.1981x; 1.9634x over previous
#include <cuda_runtime.h>
#include <cstdint>

#define NN 4096
#define CC 8
#define BB 2
#define PP 16          // B*C
#define MAXDET 100
#define SCORE_THR 0.01f
#define INVKEY26 0x3FFFFFFu      // > any valid key26 (max valid = 0x35C28F5)

// ---------------- static scratch (no runtime allocation allowed) ----------------
// cand key layout: [key26:26 | c:3 | n:12]  (41 bits); pads: [INVKEY26 | c:3 | slot:12]
// all 1600 keys globally unique; per-class list sorted ascending
__device__ unsigned long long g_cand[BB][CC * MAXDET];
__device__ unsigned int       g_ticket[BB];    // monotone; (t&7)==7 -> last CTA of batch

// exact replica of: fl(inter / max(union,1e-9)) > 0.5   (reference fp32 rounding)
__device__ __forceinline__ bool iou_gt_half(float4 a, float aa, float4 b, float ab) {
    float ix1 = fmaxf(a.x, b.x);
    float iy1 = fmaxf(a.y, b.y);
    float ix2 = fminf(a.z, b.z);
    float iy2 = fminf(a.w, b.w);
    float iw = fmaxf(ix2 - ix1, 0.0f);
    float ih = fmaxf(iy2 - iy1, 0.0f);
    float inter = iw * ih;
    float uni = (aa + ab) - inter;
    float d = fmaf(-0.5f, uni, inter);        // sign is exact
    bool gt = d > 0.0f;
    if (fabsf(d) <= 1e-5f * uni) {            // borderline: do the real division
        gt = __fdiv_rn(inter, fmaxf(uni, 1e-9f)) > 0.5f;
    }
    return gt;
}

// smem layout (dynamic): sbox[4096] f4 | skeys[4096] u64 | hist[4096] u32 | off[4096] u32 | wsum[32]
#define SM_BOX   0
#define SM_KEYS  65536
#define SM_HIST  98304
#define SM_OFF   114688
#define SM_WSUM  131072
#define SM_TOTAL 131200

// ---- fully fused: bucket-sort + chunk-parallel NMS + (last CTA) top-100 ---------
__global__ __launch_bounds__(1024) void fused_kernel(const float* __restrict__ cls,
                                                     const float* __restrict__ boxes,
                                                     const float* __restrict__ rot,
                                                     const float* __restrict__ trans,
                                                     float* __restrict__ out) {
    extern __shared__ char dyn[];
    float4*             sbox  = reinterpret_cast<float4*>(dyn + SM_BOX);
    unsigned long long* skeys = reinterpret_cast<unsigned long long*>(dyn + SM_KEYS);
    unsigned int*       hist  = reinterpret_cast<unsigned int*>(dyn + SM_HIST);
    unsigned int*       off   = reinterpret_cast<unsigned int*>(dyn + SM_OFF);
    unsigned int*       wsum  = reinterpret_cast<unsigned int*>(dyn + SM_WSUM);

    __shared__ float4       keptBox[132];     // kept set (can overshoot 100 by <32)
    __shared__ float        keptArea[132];
    __shared__ unsigned int sSup[32];         // per chunk-box: suppressed-by-kept / invalid
    __shared__ unsigned int sCross[32];       // per chunk-box: intra-chunk IoU>0.5 mask
    __shared__ int          sAnyInvalid;
    __shared__ int          sLast;

    int p = blockIdx.x;          // 0..15
    int b = p >> 3;
    int c = p & 7;
    int tid = threadIdx.x;
    int lane = tid & 31, wid = tid >> 5;

    const float4* bx4 = reinterpret_cast<const float4*>(boxes) + (b << 12);
    // cls[B][N][8] as float4 pairs: (n,c) -> float4 index n*2 + (c>>2), comp c&3
    const float4* cls4 = reinterpret_cast<const float4*>(cls) + ((size_t)b << 13);
    int chalf = c >> 2, ccomp = c & 3;

    // zero histogram (uint4) + stage boxes into smem
    reinterpret_cast<uint4*>(hist)[tid] = make_uint4(0u, 0u, 0u, 0u);
#pragma unroll
    for (int e = 0; e < 4; e++) { int i = tid + e * 1024; sbox[i] = __ldg(&bx4[i]); }
    if (tid == 0) sAnyInvalid = 0;

    // build 38-bit keys [key26 | n:12]; key26 = 0x3F800000 - bits(s), exact order
    unsigned long long keys[4];
    unsigned int bkt[4];
#pragma unroll
    for (int e = 0; e < 4; e++) {
        int n = tid * 4 + e;
        float4 v = __ldg(&cls4[n * 2 + chalf]);
        float s = (ccomp == 0) ? v.x : (ccomp == 1) ? v.y : (ccomp == 2) ? v.z : v.w;
        unsigned int sb = __float_as_uint(s);
        unsigned int k26;
        if (s > SCORE_THR) {
            k26 = (sb >= 0x3F800000u) ? 0u : (0x3F800000u - sb);   // clamp guard
        } else {
            k26 = INVKEY26;                                        // sorts last
        }
        keys[e] = ((unsigned long long)k26 << 12) | (unsigned int)n;
        bkt[e] = k26 >> 14;
    }
    __syncthreads();

#pragma unroll
    for (int e = 0; e < 4; e++) atomicAdd(&hist[bkt[e]], 1u);
    __syncthreads();

    // exclusive scan of 4096 bins (4/thread + warp shfl + warp-of-warps)
    uint4 hv = reinterpret_cast<uint4*>(hist)[tid];
    unsigned int c0 = hv.x, c1 = hv.y, c2 = hv.z, c3 = hv.w;
    unsigned int s01 = c0 + c1, sum = s01 + c2 + c3;
    unsigned int inc = sum;
#pragma unroll
    for (int d = 1; d < 32; d <<= 1) {
        unsigned int v = __shfl_up_sync(0xffffffffu, inc, d);
        if (lane >= d) inc += v;
    }
    if (lane == 31) wsum[wid] = inc;
    __syncthreads();
    if (wid == 0) {
        unsigned int v = wsum[lane], wi = v;
#pragma unroll
        for (int d = 1; d < 32; d <<= 1) {
            unsigned int u = __shfl_up_sync(0xffffffffu, wi, d);
            if (lane >= d) wi += u;
        }
        wsum[lane] = wi - v;     // exclusive
    }
    __syncthreads();
    unsigned int base = wsum[wid] + (inc - sum);
    reinterpret_cast<uint4*>(off)[tid] =
        make_uint4(base, base + c0, base + s01, base + s01 + c2);
    __syncthreads();

    // scatter (off[bk] becomes end-of-bucket)
#pragma unroll
    for (int e = 0; e < 4; e++) {
        unsigned int pos = atomicAdd(&off[bkt[e]], 1u);
        skeys[pos] = keys[e];
    }
    __syncthreads();

    // per-bucket insertion sort (tiny runs; skip invalid bucket 4095 — never sorted-read)
#pragma unroll
    for (int e = 0; e < 4; e++) {
        int bk = tid + e * 1024;
        int sz = (int)hist[bk];
        if (bk != 4095 && sz > 1) {
            int st = (int)off[bk] - sz;
            for (int i = 1; i < sz; i++) {
                unsigned long long v = skeys[st + i];
                int q = st + i;
                while (q > st && skeys[q - 1] > v) { skeys[q] = skeys[q - 1]; q--; }
                skeys[q] = v;
            }
        }
    }
    __syncthreads();

    // -------- chunk-parallel greedy NMS (all 32 warps), early stop at 100 --------
    int kept0 = 0;
    for (int j0 = 0; j0 < NN; j0 += 32) {
        // phase 1 (warp w handles chunk box w)
        {
            unsigned long long keyW = skeys[j0 + wid];           // broadcast
            unsigned int k26w = (unsigned int)(keyW >> 12);
            bool validW = (k26w != INVKEY26);
            int nW = (int)(keyW & 4095u);
            float4 bw = sbox[nW];
            float aw = (bw.z - bw.x) * (bw.w - bw.y);

            // vs kept set (kept0 <= 99 here)
            bool sup = false;
            if (lane      < kept0) sup |= iou_gt_half(keptBox[lane     ], keptArea[lane     ], bw, aw);
            if (lane + 32 < kept0) sup |= iou_gt_half(keptBox[lane + 32], keptArea[lane + 32], bw, aw);
            if (lane + 64 < kept0) sup |= iou_gt_half(keptBox[lane + 64], keptArea[lane + 64], bw, aw);
            if (lane + 96 < kept0) sup |= iou_gt_half(keptBox[lane + 96], keptArea[lane + 96], bw, aw);
            unsigned int balK = __ballot_sync(0xffffffffu, sup);

            // intra-chunk cross mask: lane j tests box j vs box w
            unsigned long long keyL = skeys[j0 + lane];
            int nL = (int)(keyL & 4095u);
            float4 bl = sbox[nL];
            float al = (bl.z - bl.x) * (bl.w - bl.y);
            unsigned int balC = __ballot_sync(0xffffffffu, iou_gt_half(bl, al, bw, aw));

            if (lane == 0) {
                sSup[wid] = (balK != 0u || !validW) ? 1u : 0u;
                sCross[wid] = balC;
                if (!validW) sAnyInvalid = 1;
            }
        }
        __syncthreads();

        // phase 2: greedy resolution over 32 bits (redundant in every thread)
        unsigned int keptNewM = 0;
        {
            unsigned int aliveM = 0;
#pragma unroll
            for (int w = 0; w < 32; w++) aliveM |= (sSup[w] ? 0u : (1u << w));
#pragma unroll
            for (int w = 0; w < 32; w++) {
                if ((aliveM >> w) & 1u) {
                    keptNewM |= 1u << w;
                    aliveM &= ~(sCross[w] & (0xFFFFFFFEu << w));
                }
            }
        }
        int stop = sAnyInvalid;

        // phase 3: parallel append (warp 0 lanes)
        if (tid < 32 && ((keptNewM >> tid) & 1u)) {
            int pos = kept0 + __popc(keptNewM & ((1u << tid) - 1u));
            unsigned long long key = skeys[j0 + tid];
            int n = (int)(key & 4095u);
            float4 bx = sbox[n];
            keptBox[pos] = bx;
            keptArea[pos] = (bx.z - bx.x) * (bx.w - bx.y);
            if (pos < MAXDET)
                g_cand[b][c * MAXDET + pos] =
                    ((key >> 12) << 15) | (unsigned int)((c << 12) | n);
        }
        kept0 += __popc(keptNewM);
        __syncthreads();

        if (kept0 >= MAXDET || stop) break;
    }

    // pad unused slots: unique keys > all valid keys (per-class ascending)
    int kk = min(kept0, MAXDET);
    for (int t = kk + tid; t < MAXDET; t += 1024)
        g_cand[b][c * MAXDET + t] =
            ((unsigned long long)INVKEY26 << 15) | (unsigned int)((c << 12) | t);

    __threadfence();                 // publish this CTA's g_cand (all threads)
    __syncthreads();
    if (tid == 0) {
        unsigned int t = atomicAdd(&g_ticket[b], 1u);
        int last = ((t & 7u) == 7u) ? 1 : 0;
        __threadfence();             // acquire: order g_cand reads after ticket
        sLast = last;
    }
    __syncthreads();

    if (!sLast) return;

    // -------- last CTA of batch b: rank 800 candidates, write top-100 ------------
    unsigned long long* sk = skeys;      // reuse (our own sort data is dead now)
    if (tid < CC * MAXDET) sk[tid] = __ldcg(&g_cand[b][tid]);   // L2-coherent read
    __syncthreads();

    if (tid < CC * MAXDET) {
        unsigned long long my = sk[tid];
        int cl = tid / MAXDET;
        int rank = tid - cl * MAXDET;    // slot within own (sorted, unique) list
#pragma unroll
        for (int c2 = 0; c2 < CC; c2++) {
            if (c2 == cl) continue;
            const unsigned long long* lst = &sk[c2 * MAXDET];
            int lo = 0, hi = MAXDET;     // lower_bound (keys globally unique)
            while (lo < hi) {
                int mid = (lo + hi) >> 1;
                if (lst[mid] < my) lo = mid + 1; else hi = mid;
            }
            rank += lo;
        }

        if (rank < MAXDET) {
            unsigned int k26 = (unsigned int)(my >> 15);
            bool ok = (k26 != INVKEY26);
            float b0 = -1.f, b1 = -1.f, b2 = -1.f, b3 = -1.f;
            float sc = -1.f, lab = -1.f;
            float r0 = -1.f, r1 = -1.f, r2 = -1.f;
            float t0 = -1.f, t1 = -1.f, t2 = -1.f;
            if (ok) {
                int cdec = (int)((my >> 12) & 7u);
                int n = (int)(my & 4095u);
                sc = __uint_as_float(0x3F800000u - k26);   // exact decode
                lab = (float)cdec;
                float4 bb4 = sbox[n];                      // our batch's boxes (smem)
                b0 = bb4.x; b1 = bb4.y; b2 = bb4.z; b3 = bb4.w;
                int base3 = ((b << 12) + n) * 3;
                r0 = rot[base3 + 0]; r1 = rot[base3 + 1]; r2 = rot[base3 + 2];
                t0 = trans[base3 + 0]; t1 = trans[base3 + 1]; t2 = trans[base3 + 2];
            }
            // layout: boxes[B,100,4] | scores[B,100] | labels[B,100] | rot[B,100,3] | trans[B,100,3]
            int r = rank;
            float* obox = out;                       // 0    .. 800
            float* osc  = out + BB * MAXDET * 4;     // 800  .. 1000
            float* olab = osc + BB * MAXDET;         // 1000 .. 1200
            float* orot = olab + BB * MAXDET;        // 1200 .. 1800
            float* otr  = orot + BB * MAXDET * 3;    // 1800 .. 2400
            obox[(b * MAXDET + r) * 4 + 0] = b0;
            obox[(b * MAXDET + r) * 4 + 1] = b1;
            obox[(b * MAXDET + r) * 4 + 2] = b2;
            obox[(b * MAXDET + r) * 4 + 3] = b3;
            osc[b * MAXDET + r] = sc;
            olab[b * MAXDET + r] = lab;
            orot[(b * MAXDET + r) * 3 + 0] = r0;
            orot[(b * MAXDET + r) * 3 + 1] = r1;
            orot[(b * MAXDET + r) * 3 + 2] = r2;
            otr[(b * MAXDET + r) * 3 + 0] = t0;
            otr[(b * MAXDET + r) * 3 + 1] = t1;
            otr[(b * MAXDET + r) * 3 + 2] = t2;
        }
    }
}

extern "C" void kernel_launch(void* const* d_in, const int* in_sizes, int n_in,
                              void* d_out, int out_size) {
    const float* boxes = (const float*)d_in[0];
    const float* cls   = (const float*)d_in[1];
    const float* rot   = (const float*)d_in[2];
    const float* trans = (const float*)d_in[3];
    float* out = (float*)d_out;
    (void)in_sizes; (void)n_in; (void)out_size;

    cudaFuncSetAttribute(fused_kernel,
                         cudaFuncAttributeMaxDynamicSharedMemorySize, SM_TOTAL);

    fused_kernel<<<PP, 1024, SM_TOTAL>>>(cls, boxes, rot, trans, out);
}

// round 12
// speedup vs baseline: 3.4636x; 1.0830x over previous
#include <cuda_runtime.h>
#include <cstdint>

#define NN 4096
#define CC 8
#define BB 2
#define PP 16          // B*C
#define MAXDET 100
#define SCORE_THR 0.01f
#define INVKEY26 0x3FFFFFFu      // > any valid key26 (max valid = 0x35C28F5)

// ---------------- static scratch (no runtime allocation allowed) ----------------
// cand key layout: [key26:26 | c:3 | n:12]  (41 bits); pads: [INVKEY26 | c:3 | slot:12]
// all 1600 keys globally unique; per-class list sorted ascending
__device__ unsigned long long g_cand[BB][CC * MAXDET];
__device__ unsigned int       g_ticket[BB];    // monotone; (t&7)==7 -> last CTA of batch

// exact replica of: fl(inter / max(union,1e-9)) > 0.5   (reference fp32 rounding)
__device__ __forceinline__ bool iou_gt_half(float4 a, float aa, float4 b, float ab) {
    float ix1 = fmaxf(a.x, b.x);
    float iy1 = fmaxf(a.y, b.y);
    float ix2 = fminf(a.z, b.z);
    float iy2 = fminf(a.w, b.w);
    float iw = fmaxf(ix2 - ix1, 0.0f);
    float ih = fmaxf(iy2 - iy1, 0.0f);
    float inter = iw * ih;
    float uni = (aa + ab) - inter;
    float d = fmaf(-0.5f, uni, inter);        // sign is exact
    bool gt = d > 0.0f;
    if (fabsf(d) <= 1e-5f * uni) {            // borderline: do the real division
        gt = __fdiv_rn(inter, fmaxf(uni, 1e-9f)) > 0.5f;
    }
    return gt;
}

// smem layout (dynamic): sbox[4096] f4 | skeys[4096] u64 | hist[4096] u32 | off[4096] u32 | wsum[32]
#define SM_BOX   0
#define SM_KEYS  65536
#define SM_HIST  98304
#define SM_OFF   114688
#define SM_WSUM  131072
#define SM_TOTAL 131200

// ---- fully fused: bucket-sort + chunk-parallel NMS + (last CTA) top-100 ---------
__global__ __launch_bounds__(1024) void fused_kernel(const float* __restrict__ cls,
                                                     const float* __restrict__ boxes,
                                                     const float* __restrict__ rot,
                                                     const float* __restrict__ trans,
                                                     float* __restrict__ out) {
    extern __shared__ char dyn[];
    float4*             sbox  = reinterpret_cast<float4*>(dyn + SM_BOX);
    unsigned long long* skeys = reinterpret_cast<unsigned long long*>(dyn + SM_KEYS);
    unsigned int*       hist  = reinterpret_cast<unsigned int*>(dyn + SM_HIST);
    unsigned int*       off   = reinterpret_cast<unsigned int*>(dyn + SM_OFF);
    unsigned int*       wsum  = reinterpret_cast<unsigned int*>(dyn + SM_WSUM);

    __shared__ float4       keptBox[132];     // kept set (can overshoot 100 by <32)
    __shared__ float        keptArea[132];
    __shared__ unsigned int sSup[32];         // per chunk-box: suppressed-by-kept / invalid
    __shared__ unsigned int sCross[32];       // per chunk-box: intra-chunk IoU>0.5 mask
    __shared__ int          sAnyInvalid;
    __shared__ int          sLast;

    int p = blockIdx.x;          // 0..15
    int b = p >> 3;
    int c = p & 7;
    int tid = threadIdx.x;
    int lane = tid & 31, wid = tid >> 5;

    const float4* bx4 = reinterpret_cast<const float4*>(boxes) + (b << 12);
    // cls[B][N][8] as float4 pairs: (n,c) -> float4 index n*2 + (c>>2), comp c&3
    const float4* cls4 = reinterpret_cast<const float4*>(cls) + ((size_t)b << 13);
    int chalf = c >> 2, ccomp = c & 3;

    // zero histogram (uint4) + stage boxes into smem
    reinterpret_cast<uint4*>(hist)[tid] = make_uint4(0u, 0u, 0u, 0u);
#pragma unroll
    for (int e = 0; e < 4; e++) { int i = tid + e * 1024; sbox[i] = __ldg(&bx4[i]); }
    if (tid == 0) sAnyInvalid = 0;

    // build 38-bit keys [key26 | n:12]; key26 = 0x3F800000 - bits(s), exact order.
    // n = e*1024 + tid -> consecutive lanes hit consecutive n (4 lanes share a line).
    // bucket by VALUE (uniform density): bkt = floor((1-s)*4096), weakly monotone
    // in key26, so concat of sorted buckets == exact global sorted order.
    unsigned long long keys[4];
    unsigned int bkt[4];
#pragma unroll
    for (int e = 0; e < 4; e++) {
        int n = e * 1024 + tid;
        float4 v = __ldg(&cls4[n * 2 + chalf]);
        float s = (ccomp == 0) ? v.x : (ccomp == 1) ? v.y : (ccomp == 2) ? v.z : v.w;
        unsigned int sb = __float_as_uint(s);
        unsigned int k26;
        unsigned int bk;
        if (s > SCORE_THR) {
            k26 = (sb >= 0x3F800000u) ? 0u : (0x3F800000u - sb);   // clamp guard
            int bi = (int)((1.0f - s) * 4096.0f);
            bk = (unsigned int)min(4094, max(0, bi));
        } else {
            k26 = INVKEY26;                                        // sorts last
            bk = 4095u;
        }
        keys[e] = ((unsigned long long)k26 << 12) | (unsigned int)n;
        bkt[e] = bk;
    }
    __syncthreads();

#pragma unroll
    for (int e = 0; e < 4; e++) atomicAdd(&hist[bkt[e]], 1u);
    __syncthreads();

    // exclusive scan of 4096 bins (4/thread + warp shfl + warp-of-warps)
    uint4 hv = reinterpret_cast<uint4*>(hist)[tid];
    unsigned int c0 = hv.x, c1 = hv.y, c2 = hv.z, c3 = hv.w;
    unsigned int s01 = c0 + c1, sum = s01 + c2 + c3;
    unsigned int inc = sum;
#pragma unroll
    for (int d = 1; d < 32; d <<= 1) {
        unsigned int v = __shfl_up_sync(0xffffffffu, inc, d);
        if (lane >= d) inc += v;
    }
    if (lane == 31) wsum[wid] = inc;
    __syncthreads();
    if (wid == 0) {
        unsigned int v = wsum[lane], wi = v;
#pragma unroll
        for (int d = 1; d < 32; d <<= 1) {
            unsigned int u = __shfl_up_sync(0xffffffffu, wi, d);
            if (lane >= d) wi += u;
        }
        wsum[lane] = wi - v;     // exclusive
    }
    __syncthreads();
    unsigned int base = wsum[wid] + (inc - sum);
    reinterpret_cast<uint4*>(off)[tid] =
        make_uint4(base, base + c0, base + s01, base + s01 + c2);
    __syncthreads();

    // scatter (off[bk] becomes end-of-bucket)
#pragma unroll
    for (int e = 0; e < 4; e++) {
        unsigned int pos = atomicAdd(&off[bkt[e]], 1u);
        skeys[pos] = keys[e];
    }
    __syncthreads();

    // per-bucket insertion sort (runs ~Poisson(1); skip invalid bucket 4095)
#pragma unroll
    for (int e = 0; e < 4; e++) {
        int bk = tid + e * 1024;
        int sz = (int)hist[bk];
        if (bk != 4095 && sz > 1) {
            int st = (int)off[bk] - sz;
            for (int i = 1; i < sz; i++) {
                unsigned long long v = skeys[st + i];
                int q = st + i;
                while (q > st && skeys[q - 1] > v) { skeys[q] = skeys[q - 1]; q--; }
                skeys[q] = v;
            }
        }
    }
    __syncthreads();

    // -------- chunk-parallel greedy NMS (all 32 warps), early stop at 100 --------
    int kept0 = 0;
    for (int j0 = 0; j0 < NN; j0 += 32) {
        // phase 1 (warp w handles chunk box w)
        {
            unsigned long long keyW = skeys[j0 + wid];           // broadcast
            unsigned int k26w = (unsigned int)(keyW >> 12);
            bool validW = (k26w != INVKEY26);
            int nW = (int)(keyW & 4095u);
            float4 bw = sbox[nW];
            float aw = (bw.z - bw.x) * (bw.w - bw.y);

            // vs kept set (kept0 <= 99 here)
            bool sup = false;
            if (lane      < kept0) sup |= iou_gt_half(keptBox[lane     ], keptArea[lane     ], bw, aw);
            if (lane + 32 < kept0) sup |= iou_gt_half(keptBox[lane + 32], keptArea[lane + 32], bw, aw);
            if (lane + 64 < kept0) sup |= iou_gt_half(keptBox[lane + 64], keptArea[lane + 64], bw, aw);
            if (lane + 96 < kept0) sup |= iou_gt_half(keptBox[lane + 96], keptArea[lane + 96], bw, aw);
            unsigned int balK = __ballot_sync(0xffffffffu, sup);

            // intra-chunk cross mask: lane j tests box j vs box w
            unsigned long long keyL = skeys[j0 + lane];
            int nL = (int)(keyL & 4095u);
            float4 bl = sbox[nL];
            float al = (bl.z - bl.x) * (bl.w - bl.y);
            unsigned int balC = __ballot_sync(0xffffffffu, iou_gt_half(bl, al, bw, aw));

            if (lane == 0) {
                sSup[wid] = (balK != 0u || !validW) ? 1u : 0u;
                sCross[wid] = balC;
                if (!validW) sAnyInvalid = 1;
            }
        }
        __syncthreads();

        // phase 2: greedy resolution over 32 bits (redundant in every thread)
        unsigned int keptNewM = 0;
        {
            unsigned int aliveM = 0;
#pragma unroll
            for (int w = 0; w < 32; w++) aliveM |= (sSup[w] ? 0u : (1u << w));
#pragma unroll
            for (int w = 0; w < 32; w++) {
                if ((aliveM >> w) & 1u) {
                    keptNewM |= 1u << w;
                    aliveM &= ~(sCross[w] & (0xFFFFFFFEu << w));
                }
            }
        }
        int stop = sAnyInvalid;

        // phase 3: parallel append (warp 0 lanes)
        if (tid < 32 && ((keptNewM >> tid) & 1u)) {
            int pos = kept0 + __popc(keptNewM & ((1u << tid) - 1u));
            unsigned long long key = skeys[j0 + tid];
            int n = (int)(key & 4095u);
            float4 bx = sbox[n];
            keptBox[pos] = bx;
            keptArea[pos] = (bx.z - bx.x) * (bx.w - bx.y);
            if (pos < MAXDET)
                g_cand[b][c * MAXDET + pos] =
                    ((key >> 12) << 15) | (unsigned int)((c << 12) | n);
        }
        kept0 += __popc(keptNewM);
        __syncthreads();

        if (kept0 >= MAXDET || stop) break;
    }

    // pad unused slots: unique keys > all valid keys (per-class ascending)
    int kk = min(kept0, MAXDET);
    for (int t = kk + tid; t < MAXDET; t += 1024)
        g_cand[b][c * MAXDET + t] =
            ((unsigned long long)INVKEY26 << 15) | (unsigned int)((c << 12) | t);

    __threadfence();                 // publish this CTA's g_cand (all threads)
    __syncthreads();
    if (tid == 0) {
        unsigned int t = atomicAdd(&g_ticket[b], 1u);
        int last = ((t & 7u) == 7u) ? 1 : 0;
        __threadfence();             // acquire: order g_cand reads after ticket
        sLast = last;
    }
    __syncthreads();

    if (!sLast) return;

    // -------- last CTA of batch b: rank 800 candidates, write top-100 ------------
    unsigned long long* sk = skeys;      // reuse (our own sort data is dead now)
    if (tid < CC * MAXDET) sk[tid] = __ldcg(&g_cand[b][tid]);   // L2-coherent read
    __syncthreads();

    if (tid < CC * MAXDET) {
        unsigned long long my = sk[tid];
        int cl = tid / MAXDET;
        int rank = tid - cl * MAXDET;    // slot within own (sorted, unique) list
#pragma unroll
        for (int c2 = 0; c2 < CC; c2++) {
            if (c2 == cl) continue;
            const unsigned long long* lst = &sk[c2 * MAXDET];
            int lo = 0, hi = MAXDET;     // lower_bound (keys globally unique)
            while (lo < hi) {
                int mid = (lo + hi) >> 1;
                if (lst[mid] < my) lo = mid + 1; else hi = mid;
            }
            rank += lo;
        }

        if (rank < MAXDET) {
            unsigned int k26 = (unsigned int)(my >> 15);
            bool ok = (k26 != INVKEY26);
            float b0 = -1.f, b1 = -1.f, b2 = -1.f, b3 = -1.f;
            float sc = -1.f, lab = -1.f;
            float r0 = -1.f, r1 = -1.f, r2 = -1.f;
            float t0 = -1.f, t1 = -1.f, t2 = -1.f;
            if (ok) {
                int cdec = (int)((my >> 12) & 7u);
                int n = (int)(my & 4095u);
                sc = __uint_as_float(0x3F800000u - k26);   // exact decode
                lab = (float)cdec;
                float4 bb4 = sbox[n];                      // our batch's boxes (smem)
                b0 = bb4.x; b1 = bb4.y; b2 = bb4.z; b3 = bb4.w;
                int base3 = ((b << 12) + n) * 3;
                r0 = rot[base3 + 0]; r1 = rot[base3 + 1]; r2 = rot[base3 + 2];
                t0 = trans[base3 + 0]; t1 = trans[base3 + 1]; t2 = trans[base3 + 2];
            }
            // layout: boxes[B,100,4] | scores[B,100] | labels[B,100] | rot[B,100,3] | trans[B,100,3]
            int r = rank;
            float* obox = out;                       // 0    .. 800
            float* osc  = out + BB * MAXDET * 4;     // 800  .. 1000
            float* olab = osc + BB * MAXDET;         // 1000 .. 1200
            float* orot = olab + BB * MAXDET;        // 1200 .. 1800
            float* otr  = orot + BB * MAXDET * 3;    // 1800 .. 2400
            obox[(b * MAXDET + r) * 4 + 0] = b0;
            obox[(b * MAXDET + r) * 4 + 1] = b1;
            obox[(b * MAXDET + r) * 4 + 2] = b2;
            obox[(b * MAXDET + r) * 4 + 3] = b3;
            osc[b * MAXDET + r] = sc;
            olab[b * MAXDET + r] = lab;
            orot[(b * MAXDET + r) * 3 + 0] = r0;
            orot[(b * MAXDET + r) * 3 + 1] = r1;
            orot[(b * MAXDET + r) * 3 + 2] = r2;
            otr[(b * MAXDET + r) * 3 + 0] = t0;
            otr[(b * MAXDET + r) * 3 + 1] = t1;
            otr[(b * MAXDET + r) * 3 + 2] = t2;
        }
    }
}

extern "C" void kernel_launch(void* const* d_in, const int* in_sizes, int n_in,
                              void* d_out, int out_size) {
    const float* boxes = (const float*)d_in[0];
    const float* cls   = (const float*)d_in[1];
    const float* rot   = (const float*)d_in[2];
    const float* trans = (const float*)d_in[3];
    float* out = (float*)d_out;
    (void)in_sizes; (void)n_in; (void)out_size;

    cudaFuncSetAttribute(fused_kernel,
                         cudaFuncAttributeMaxDynamicSharedMemorySize, SM_TOTAL);

    fused_kernel<<<PP, 1024, SM_TOTAL>>>(cls, boxes, rot, trans, out);
}

// round 14
// speedup vs baseline: 4.1341x; 1.1936x over previous
#include <cuda_runtime.h>
#include <cstdint>

#define NN 4096
#define CC 8
#define BB 2
#define PP 16          // B*C
#define MAXDET 100
#define SCORE_THR 0.01f
#define INVKEY26 0x3FFFFFFu      // > any valid key26 (max valid = 0x35C28F5)

// ---------------- static scratch (no runtime allocation allowed) ----------------
// cand key layout: [key26:26 | c:3 | n:12]  (41 bits); pads: [INVKEY26 | c:3 | slot:12]
// all 1600 keys globally unique; per-class list sorted ascending
__device__ unsigned long long g_cand[BB][CC * MAXDET];
__device__ unsigned int       g_ticket[BB];    // monotone; (t&7)==7 -> last CTA of batch

// exact replica of: fl(inter / max(union,1e-9)) > 0.5   (reference fp32 rounding)
__device__ __forceinline__ bool iou_gt_half(float4 a, float aa, float4 b, float ab) {
    float ix1 = fmaxf(a.x, b.x);
    float iy1 = fmaxf(a.y, b.y);
    float ix2 = fminf(a.z, b.z);
    float iy2 = fminf(a.w, b.w);
    float iw = fmaxf(ix2 - ix1, 0.0f);
    float ih = fmaxf(iy2 - iy1, 0.0f);
    float inter = iw * ih;
    float uni = (aa + ab) - inter;
    float d = fmaf(-0.5f, uni, inter);        // sign is exact
    bool gt = d > 0.0f;
    if (fabsf(d) <= 1e-5f * uni) {            // borderline: do the real division
        gt = __fdiv_rn(inter, fmaxf(uni, 1e-9f)) > 0.5f;
    }
    return gt;
}

// smem layout (dynamic): sbox[4096] f4 | skeys[4096] u64 | hist[4096] u32 | off[4096] u32 | wsum[32]
#define SM_BOX   0
#define SM_KEYS  65536
#define SM_HIST  98304
#define SM_OFF   114688
#define SM_WSUM  131072
#define SM_TOTAL 131200

// ---- fully fused: bucket-sort + chunk-parallel NMS + (last CTA) top-100 ---------
__global__ __launch_bounds__(1024) void fused_kernel(const float* __restrict__ cls,
                                                     const float* __restrict__ boxes,
                                                     const float* __restrict__ rot,
                                                     const float* __restrict__ trans,
                                                     float* __restrict__ out) {
    extern __shared__ char dyn[];
    float4*             sbox  = reinterpret_cast<float4*>(dyn + SM_BOX);
    unsigned long long* skeys = reinterpret_cast<unsigned long long*>(dyn + SM_KEYS);
    unsigned int*       hist  = reinterpret_cast<unsigned int*>(dyn + SM_HIST);
    unsigned int*       off   = reinterpret_cast<unsigned int*>(dyn + SM_OFF);
    unsigned int*       wsum  = reinterpret_cast<unsigned int*>(dyn + SM_WSUM);

    __shared__ float4       keptBox[132];     // kept set (can overshoot 100 by <32)
    __shared__ float        keptArea[132];
    __shared__ unsigned int sSup[32];         // per chunk-box: suppressed-by-kept / invalid
    __shared__ unsigned int sCross[32];       // per chunk-box: intra-chunk IoU>0.5 mask
    __shared__ int          sAnyInvalid;
    __shared__ int          sKept0;
    __shared__ int          sLast;

    int p = blockIdx.x;          // 0..15
    int b = p >> 3;
    int c = p & 7;
    int tid = threadIdx.x;
    int lane = tid & 31, wid = tid >> 5;

    const float4* bx4 = reinterpret_cast<const float4*>(boxes) + (b << 12);
    // cls[B][N][8] as float4 pairs: (n,c) -> float4 index n*2 + (c>>2), comp c&3
    const float4* cls4 = reinterpret_cast<const float4*>(cls) + ((size_t)b << 13);
    int chalf = c >> 2, ccomp = c & 3;

    // zero histogram (uint4) + stage boxes into smem
    reinterpret_cast<uint4*>(hist)[tid] = make_uint4(0u, 0u, 0u, 0u);
#pragma unroll
    for (int e = 0; e < 4; e++) { int i = tid + e * 1024; sbox[i] = __ldg(&bx4[i]); }
    if (tid == 0) sAnyInvalid = 0;

    // build 38-bit keys [key26 | n:12]; key26 = 0x3F800000 - bits(s), exact order.
    // bucket by VALUE (uniform density): bkt = floor((1-s)*4096), weakly monotone
    // in key26, so concat of sorted buckets == exact global sorted order.
    unsigned long long keys[4];
    unsigned int bkt[4];
#pragma unroll
    for (int e = 0; e < 4; e++) {
        int n = e * 1024 + tid;
        float4 v = __ldg(&cls4[n * 2 + chalf]);
        float s = (ccomp == 0) ? v.x : (ccomp == 1) ? v.y : (ccomp == 2) ? v.z : v.w;
        unsigned int sb = __float_as_uint(s);
        unsigned int k26;
        unsigned int bk;
        if (s > SCORE_THR) {
            k26 = (sb >= 0x3F800000u) ? 0u : (0x3F800000u - sb);   // clamp guard
            int bi = (int)((1.0f - s) * 4096.0f);
            bk = (unsigned int)min(4094, max(0, bi));
        } else {
            k26 = INVKEY26;                                        // sorts last
            bk = 4095u;
        }
        keys[e] = ((unsigned long long)k26 << 12) | (unsigned int)n;
        bkt[e] = bk;
    }
    __syncthreads();

#pragma unroll
    for (int e = 0; e < 4; e++) atomicAdd(&hist[bkt[e]], 1u);
    __syncthreads();

    // exclusive scan of 4096 bins (4/thread + warp shfl + warp-of-warps)
    uint4 hv = reinterpret_cast<uint4*>(hist)[tid];
    unsigned int c0 = hv.x, c1 = hv.y, c2 = hv.z, c3 = hv.w;
    unsigned int s01 = c0 + c1, sum = s01 + c2 + c3;
    unsigned int inc = sum;
#pragma unroll
    for (int d = 1; d < 32; d <<= 1) {
        unsigned int v = __shfl_up_sync(0xffffffffu, inc, d);
        if (lane >= d) inc += v;
    }
    if (lane == 31) wsum[wid] = inc;
    __syncthreads();
    if (wid == 0) {
        unsigned int v = wsum[lane], wi = v;
#pragma unroll
        for (int d = 1; d < 32; d <<= 1) {
            unsigned int u = __shfl_up_sync(0xffffffffu, wi, d);
            if (lane >= d) wi += u;
        }
        wsum[lane] = wi - v;     // exclusive
    }
    __syncthreads();
    unsigned int base = wsum[wid] + (inc - sum);
    reinterpret_cast<uint4*>(off)[tid] =
        make_uint4(base, base + c0, base + s01, base + s01 + c2);
    __syncthreads();

    // scatter (off[bk] becomes end-of-bucket)
#pragma unroll
    for (int e = 0; e < 4; e++) {
        unsigned int pos = atomicAdd(&off[bkt[e]], 1u);
        skeys[pos] = keys[e];
    }
    __syncthreads();

    // per-bucket insertion sort (runs ~Poisson(1); skip invalid bucket 4095)
#pragma unroll
    for (int e = 0; e < 4; e++) {
        int bk = tid + e * 1024;
        int sz = (int)hist[bk];
        if (bk != 4095 && sz > 1) {
            int st = (int)off[bk] - sz;
            for (int i = 1; i < sz; i++) {
                unsigned long long v = skeys[st + i];
                int q = st + i;
                while (q > st && skeys[q - 1] > v) { skeys[q] = skeys[q - 1]; q--; }
                skeys[q] = v;
            }
        }
    }
    __syncthreads();

    // -------- chunk-parallel greedy NMS: phase1 all warps, phase2/3 warp 0 -------
    int kept0 = 0;
    for (int j0 = 0; j0 < NN; j0 += 32) {
        // phase 1 (warp w handles chunk box w)
        {
            unsigned long long keyW = skeys[j0 + wid];           // broadcast
            unsigned int k26w = (unsigned int)(keyW >> 12);
            bool validW = (k26w != INVKEY26);
            int nW = (int)(keyW & 4095u);
            float4 bw = sbox[nW];
            float aw = (bw.z - bw.x) * (bw.w - bw.y);

            // vs kept set (kept0 <= 99 here)
            bool sup = false;
            if (lane      < kept0) sup |= iou_gt_half(keptBox[lane     ], keptArea[lane     ], bw, aw);
            if (lane + 32 < kept0) sup |= iou_gt_half(keptBox[lane + 32], keptArea[lane + 32], bw, aw);
            if (lane + 64 < kept0) sup |= iou_gt_half(keptBox[lane + 64], keptArea[lane + 64], bw, aw);
            if (lane + 96 < kept0) sup |= iou_gt_half(keptBox[lane + 96], keptArea[lane + 96], bw, aw);
            unsigned int balK = __ballot_sync(0xffffffffu, sup);

            // intra-chunk cross mask: lane j tests box j vs box w
            unsigned long long keyL = skeys[j0 + lane];
            int nL = (int)(keyL & 4095u);
            float4 bl = sbox[nL];
            float al = (bl.z - bl.x) * (bl.w - bl.y);
            unsigned int balC = __ballot_sync(0xffffffffu, iou_gt_half(bl, al, bw, aw));

            if (lane == 0) {
                sSup[wid] = (balK != 0u || !validW) ? 1u : 0u;
                sCross[wid] = balC;
                if (!validW) sAnyInvalid = 1;
            }
        }
        __syncthreads();

        // phase 2+3: warp 0 only (other warps wait — no redundant issue pressure)
        if (wid == 0) {
            unsigned int crossR = sCross[lane];                 // lane's cross mask
            unsigned int laterR = 0xFFFFFFFEu << lane;          // bits above lane (lane31 -> 0)
            unsigned int aliveM = __ballot_sync(0xffffffffu, sSup[lane] == 0u);
            unsigned int hasCross = __ballot_sync(0xffffffffu, (crossR & laterR) != 0u);

            unsigned int keptNewM;
            if ((aliveM & hasCross) == 0u) {
                keptNewM = aliveM;          // fast path: no intra-chunk suppression
            } else {
                keptNewM = 0u;
                unsigned int rem = aliveM;  // pending boxes, ascending order via ffs
                while (rem) {
                    int w = __ffs(rem) - 1;
                    rem &= rem - 1u;
                    keptNewM |= 1u << w;
                    if ((hasCross >> w) & 1u) {
                        unsigned int cw = __shfl_sync(0xffffffffu, crossR, w);
                        unsigned int kill = cw & (0xFFFFFFFEu << w);
                        aliveM &= ~kill;
                        rem &= ~kill;
                    }
                }
            }

            // phase 3: parallel append (lanes of warp 0)
            if ((keptNewM >> lane) & 1u) {
                int pos = kept0 + __popc(keptNewM & ((1u << lane) - 1u));
                unsigned long long key = skeys[j0 + lane];
                int n = (int)(key & 4095u);
                float4 bx = sbox[n];
                keptBox[pos] = bx;
                keptArea[pos] = (bx.z - bx.x) * (bx.w - bx.y);
                if (pos < MAXDET)
                    g_cand[b][c * MAXDET + pos] =
                        ((key >> 12) << 15) | (unsigned int)((c << 12) | n);
            }
            if (lane == 0) sKept0 = kept0 + __popc(keptNewM);
        }
        __syncthreads();

        kept0 = sKept0;
        if (kept0 >= MAXDET || sAnyInvalid) break;
    }

    // pad unused slots (warp 0 = sole g_cand writer); fence by writers only
    if (tid < 32) {
        int kk = min(kept0, MAXDET);
        for (int t = kk + lane; t < MAXDET; t += 32)
            g_cand[b][c * MAXDET + t] =
                ((unsigned long long)INVKEY26 << 15) | (unsigned int)((c << 12) | t);
        __threadfence();                 // release: all our g_cand writes
        __syncwarp();
        if (lane == 0) {
            unsigned int t = atomicAdd(&g_ticket[b], 1u);
            int last = ((t & 7u) == 7u) ? 1 : 0;
            __threadfence();             // acquire: order g_cand reads after ticket
            sLast = last;
        }
    }
    __syncthreads();

    if (!sLast) return;

    // -------- last CTA of batch b: rank 800 candidates, write top-100 ------------
    unsigned long long* sk = skeys;      // reuse (our own sort data is dead now)
    if (tid < CC * MAXDET) sk[tid] = __ldcg(&g_cand[b][tid]);   // L2-coherent read
    __syncthreads();

    if (tid < CC * MAXDET) {
        unsigned long long my = sk[tid];
        int cl = tid / MAXDET;
        int rank = tid - cl * MAXDET;    // slot within own (sorted, unique) list
#pragma unroll
        for (int c2 = 0; c2 < CC; c2++) {
            if (c2 == cl) continue;
            const unsigned long long* lst = &sk[c2 * MAXDET];
            int lo = 0, hi = MAXDET;     // lower_bound (keys globally unique)
            while (lo < hi) {
                int mid = (lo + hi) >> 1;
                if (lst[mid] < my) lo = mid + 1; else hi = mid;
            }
            rank += lo;
        }

        if (rank < MAXDET) {
            unsigned int k26 = (unsigned int)(my >> 15);
            bool ok = (k26 != INVKEY26);
            float b0 = -1.f, b1 = -1.f, b2 = -1.f, b3 = -1.f;
            float sc = -1.f, lab = -1.f;
            float r0 = -1.f, r1 = -1.f, r2 = -1.f;
            float t0 = -1.f, t1 = -1.f, t2 = -1.f;
            if (ok) {
                int cdec = (int)((my >> 12) & 7u);
                int n = (int)(my & 4095u);
                sc = __uint_as_float(0x3F800000u - k26);   // exact decode
                lab = (float)cdec;
                float4 bb4 = sbox[n];                      // our batch's boxes (smem)
                b0 = bb4.x; b1 = bb4.y; b2 = bb4.z; b3 = bb4.w;
                int base3 = ((b << 12) + n) * 3;
                r0 = rot[base3 + 0]; r1 = rot[base3 + 1]; r2 = rot[base3 + 2];
                t0 = trans[base3 + 0]; t1 = trans[base3 + 1]; t2 = trans[base3 + 2];
            }
            // layout: boxes[B,100,4] | scores[B,100] | labels[B,100] | rot[B,100,3] | trans[B,100,3]
            int r = rank;
            float* obox = out;                       // 0    .. 800
            float* osc  = out + BB * MAXDET * 4;     // 800  .. 1000
            float* olab = osc + BB * MAXDET;         // 1000 .. 1200
            float* orot = olab + BB * MAXDET;        // 1200 .. 1800
            float* otr  = orot + BB * MAXDET * 3;    // 1800 .. 2400
            obox[(b * MAXDET + r) * 4 + 0] = b0;
            obox[(b * MAXDET + r) * 4 + 1] = b1;
            obox[(b * MAXDET + r) * 4 + 2] = b2;
            obox[(b * MAXDET + r) * 4 + 3] = b3;
            osc[b * MAXDET + r] = sc;
            olab[b * MAXDET + r] = lab;
            orot[(b * MAXDET + r) * 3 + 0] = r0;
            orot[(b * MAXDET + r) * 3 + 1] = r1;
            orot[(b * MAXDET + r) * 3 + 2] = r2;
            otr[(b * MAXDET + r) * 3 + 0] = t0;
            otr[(b * MAXDET + r) * 3 + 1] = t1;
            otr[(b * MAXDET + r) * 3 + 2] = t2;
        }
    }
}

extern "C" void kernel_launch(void* const* d_in, const int* in_sizes, int n_in,
                              void* d_out, int out_size) {
    const float* boxes = (const float*)d_in[0];
    const float* cls   = (const float*)d_in[1];
    const float* rot   = (const float*)d_in[2];
    const float* trans = (const float*)d_in[3];
    float* out = (float*)d_out;
    (void)in_sizes; (void)n_in; (void)out_size;

    cudaFuncSetAttribute(fused_kernel,
                         cudaFuncAttributeMaxDynamicSharedMemorySize, SM_TOTAL);

    fused_kernel<<<PP, 1024, SM_TOTAL>>>(cls, boxes, rot, trans, out);
}